// round 7
// baseline (speedup 1.0000x reference)
#include <cuda_runtime.h>
#include <cstdint>

// Problem constants (fixed shapes per reference)
#define BB    256
#define VV    128000
#define LL    32
#define NNEG  1024
#define EPSF  1e-8f
#define TMARG 2.0f
#define NTHR  0.1f

// Deterministic scratch: per-row partials [self, target, margin, neg_sum]
__device__ float        g_partial[BB * 4];
__device__ unsigned int g_count = 0;   // reset by last block each call -> replay-safe

// One block per batch row, 256 threads. The last block to finish also does
// the final 256-row reduction (deterministic fixed-order tree).
//
// NOTE on dtypes: the reference declares ids as jnp.int64, but JAX without
// x64 silently downcasts to int32 — the harness delivers int32 arrays.
// (R5's long-long read faulted with ~2^47-scale indices: two packed int32s.)
__global__ __launch_bounds__(256) void fused_kernel(
    const float* __restrict__ sparse,
    const int*   __restrict__ ko_ids,
    const int*   __restrict__ ko_len,
    const int*   __restrict__ en_ids,
    const int*   __restrict__ en_len,
    const int*   __restrict__ neg_ids,
    float*       __restrict__ out)
{
    const int b = blockIdx.x;
    const int t = threadIdx.x;
    const float* __restrict__ row = sparse + (size_t)b * VV;

    float v_self = 0.0f, v_tgt = 0.0f, v_mar = 0.0f, v_neg = 0.0f;

    if (t < LL) {
        const int kl = ko_len[b];
        const int el = en_len[b];
        const int kid = ko_ids[b * LL + t];
        const int eid = en_ids[b * LL + t];
        const float ka = row[kid];
        const float ea = row[eid];
        if (t < kl) v_self = -__logf(ka + EPSF);
        if (t < el) {
            v_tgt = -__logf(ea + EPSF);
            v_mar = fmaxf(TMARG - ea, 0.0f);
        }
    }

    // Negatives: one int4 load gives 4 indices -> 4 independent gathers (MLP=4).
    {
        const int4 ids = reinterpret_cast<const int4*>(neg_ids)[t];  // 256*4 = 1024
        const float x0 = row[ids.x];
        const float x1 = row[ids.y];
        const float x2 = row[ids.z];
        const float x3 = row[ids.w];
        v_neg = fmaxf(x0 - NTHR, 0.0f) + fmaxf(x1 - NTHR, 0.0f)
              + fmaxf(x2 - NTHR, 0.0f) + fmaxf(x3 - NTHR, 0.0f);
    }

    // Warp reduction (fixed shuffle order -> deterministic)
    #pragma unroll
    for (int off = 16; off > 0; off >>= 1) {
        v_self += __shfl_down_sync(0xFFFFFFFFu, v_self, off);
        v_tgt  += __shfl_down_sync(0xFFFFFFFFu, v_tgt,  off);
        v_mar  += __shfl_down_sync(0xFFFFFFFFu, v_mar,  off);
        v_neg  += __shfl_down_sync(0xFFFFFFFFu, v_neg,  off);
    }

    __shared__ float sh[8][4];
    const int wid = t >> 5;
    if ((t & 31) == 0) {
        sh[wid][0] = v_self;
        sh[wid][1] = v_tgt;
        sh[wid][2] = v_mar;
        sh[wid][3] = v_neg;
    }
    __syncthreads();

    __shared__ bool s_last;
    if (t == 0) {
        float s0 = 0.f, s1 = 0.f, s2 = 0.f, s3 = 0.f;
        #pragma unroll
        for (int w = 0; w < 8; w++) {
            s0 += sh[w][0]; s1 += sh[w][1]; s2 += sh[w][2]; s3 += sh[w][3];
        }
        const float ck = fmaxf((float)ko_len[b], 1.0f);
        const float ce = fmaxf((float)en_len[b], 1.0f);
        // masked_mean: len==0 -> masked sum is 0, so s/max(len,1)==0 already
        // matches the jnp.where(length>0, ..., 0) branch.
        g_partial[b * 4 + 0] = s0 / ck;
        g_partial[b * 4 + 1] = s1 / ce;
        g_partial[b * 4 + 2] = s2 / ce;
        g_partial[b * 4 + 3] = s3;          // raw neg sum; scaled below
        __threadfence();
        const unsigned int ticket = atomicAdd(&g_count, 1u);
        s_last = (ticket == BB - 1);
    }
    __syncthreads();

    if (!s_last) return;

    // ---- last block: deterministic final reduction of 256 row partials ----
    __threadfence();  // acquire all g_partial writes
    __shared__ float red[256];
    #pragma unroll
    for (int k = 0; k < 4; k++) {
        red[t] = g_partial[t * 4 + k];
        __syncthreads();
        #pragma unroll
        for (int s = 128; s > 0; s >>= 1) {
            if (t < s) red[t] += red[t + s];
            __syncthreads();
        }
        if (t == 0) {
            out[k] = (k < 3) ? (red[0] / (float)BB)
                             : (red[0] / (float)(BB * NNEG));
        }
        __syncthreads();
    }
    if (t == 0) g_count = 0;   // reset for next graph replay (deterministic)
}

extern "C" void kernel_launch(void* const* d_in, const int* in_sizes, int n_in,
                              void* d_out, int out_size)
{
    const float* sparse  = (const float*)d_in[0];
    const int*   ko_ids  = (const int*)d_in[1];
    const int*   ko_len  = (const int*)d_in[2];
    const int*   en_ids  = (const int*)d_in[3];
    const int*   en_len  = (const int*)d_in[4];
    const int*   neg_ids = (const int*)d_in[5];
    float* out = (float*)d_out;

    fused_kernel<<<BB, 256>>>(sparse, ko_ids, ko_len, en_ids, en_len, neg_ids, out);
}